// round 1
// baseline (speedup 1.0000x reference)
#include <cuda_runtime.h>
#include <math.h>

// ---------------------------------------------------------------------------
// MiniStageGRU on GB300: conv-GRU gates, all convs are (2,5), pad H(1,0) W(2,2)
// B=16, Cin_x=4, C=8, T=1000, F=257.
//
// Pipeline (single stream, graph-capturable):
//   pad_x, pad_h : copy x,h into zero-padded scratch (stride FP=272, 2 left pad)
//   k1_pre       : xp = elu(conv(x, pre))                 -> g_xp (padded)
//   k2_zr        : z = sig(conv(xp,xz)+conv(h,hz))        -> g_z
//                  r = sig(conv(xp,xr)+conv(h,hr)); rh=r*h-> g_rh
//   k3_out       : n = tanh(conv(xp,xn)+conv(rh,hn))
//                  out = (1-z)*h + z*n
//
// Math path: packed fma.rn.f32x2, pairing over OUTPUT CHANNELS (each thread
// owns 4 co as 2 f32x2 pairs x 4 consecutive f). Input values are broadcast-
// packed once per window element and reused across convs and kw taps.
// Weights live in __constant__ -> uniform LDCU.
// ---------------------------------------------------------------------------

typedef unsigned long long ULL;

static __device__ __forceinline__ ULL pk(float lo, float hi) {
    ULL r;
    asm("mov.b64 %0, {%1,%2};" : "=l"(r) : "f"(lo), "f"(hi));
    return r;
}
static __device__ __forceinline__ void upk(ULL v, float& lo, float& hi) {
    asm("mov.b64 {%0,%1}, %2;" : "=f"(lo), "=f"(hi) : "l"(v));
}
static __device__ __forceinline__ ULL ffma2(ULL a, ULL b, ULL c) {
    ULL d;
    asm("fma.rn.f32x2 %0, %1, %2, %3;" : "=l"(d) : "l"(a), "l"(b), "l"(c));
    return d;
}
static __device__ __forceinline__ float sigf(float x) {
    return 1.0f / (1.0f + expf(-x));
}

constexpr int B    = 16;
constexpr int C    = 8;    // GRU channels
constexpr int CIX  = 4;    // x input channels
constexpr int T    = 1000;
constexpr int F    = 257;
constexpr int FP   = 272;  // padded stride: [2 left pad][257 data][13 right pad]
constexpr int FBLK = 65;   // f-blocks of 4 covering f0 = 0..256

constexpr int NTHREAD_MAIN = B * 2 * T * FBLK;  // 2 co-groups of 4 channels

// ---- scratch (device globals; no allocation allowed) ----------------------
__device__ __align__(16) float g_xpad[(size_t)B * CIX * T * FP];  // padded x
__device__ __align__(16) float g_hpad[(size_t)B * C   * T * FP];  // padded h
__device__ __align__(16) float g_xp  [(size_t)B * C   * T * FP];  // padded xp
__device__ __align__(16) float g_z   [(size_t)B * C   * T * FP];  // padded z
__device__ __align__(16) float g_rh  [(size_t)B * C   * T * FP];  // padded r*h

// ---- weights in constant memory -------------------------------------------
__constant__ float c_pre_w[C * CIX * 2 * 5];
__constant__ float c_pre_b[C];
__constant__ float c_xz_w[C * C * 2 * 5];
__constant__ float c_xz_b[C];
__constant__ float c_xr_w[C * C * 2 * 5];
__constant__ float c_xr_b[C];
__constant__ float c_xn_w[C * C * 2 * 5];
__constant__ float c_xn_b[C];
__constant__ float c_hz_w[C * C * 2 * 5];
__constant__ float c_hz_b[C];
__constant__ float c_hr_w[C * C * 2 * 5];
__constant__ float c_hr_b[C];
__constant__ float c_hn_w[C * C * 2 * 5];
__constant__ float c_hn_b[C];

// ---------------------------------------------------------------------------
// conv row micro-kernels.
// rowp: padded input row at f_mem = f0 (so window element m is input f0-2+m).
// w:    weight base for (co0, ci, kh): &w_tensor[((co0)*CIN + ci)*10 + kh*5]
// costr: CIN*10 (stride between consecutive co in the weight tensor)
// acc[p][j]: f32x2 pair holding channels (co0+2p, co0+2p+1), position f0+j.
// ---------------------------------------------------------------------------
static __device__ __forceinline__ void conv_row_single(
    const float* __restrict__ rowp, const float* __restrict__ w, int costr,
    ULL acc[2][4])
{
    float4 A  = *reinterpret_cast<const float4*>(rowp);
    float4 Bv = *reinterpret_cast<const float4*>(rowp + 4);
    float win[8] = {A.x, A.y, A.z, A.w, Bv.x, Bv.y, Bv.z, Bv.w};
    ULL wb[8];
#pragma unroll
    for (int m = 0; m < 8; ++m) wb[m] = pk(win[m], win[m]);
#pragma unroll
    for (int kw = 0; kw < 5; ++kw) {
#pragma unroll
        for (int p = 0; p < 2; ++p) {
            ULL wp = pk(w[(2 * p) * costr + kw], w[(2 * p + 1) * costr + kw]);
#pragma unroll
            for (int j = 0; j < 4; ++j)
                acc[p][j] = ffma2(wp, wb[j + kw], acc[p][j]);
        }
    }
}

// Two convolutions over the same input row (costr fixed at 80 = 8*10).
static __device__ __forceinline__ void conv_row_dual(
    const float* __restrict__ rowp,
    const float* __restrict__ w1, const float* __restrict__ w2,
    ULL a1[2][4], ULL a2[2][4])
{
    float4 A  = *reinterpret_cast<const float4*>(rowp);
    float4 Bv = *reinterpret_cast<const float4*>(rowp + 4);
    float win[8] = {A.x, A.y, A.z, A.w, Bv.x, Bv.y, Bv.z, Bv.w};
    ULL wb[8];
#pragma unroll
    for (int m = 0; m < 8; ++m) wb[m] = pk(win[m], win[m]);
#pragma unroll
    for (int kw = 0; kw < 5; ++kw) {
#pragma unroll
        for (int p = 0; p < 2; ++p) {
            ULL wp1 = pk(w1[(2 * p) * 80 + kw], w1[(2 * p + 1) * 80 + kw]);
            ULL wp2 = pk(w2[(2 * p) * 80 + kw], w2[(2 * p + 1) * 80 + kw]);
#pragma unroll
            for (int j = 0; j < 4; ++j) {
                a1[p][j] = ffma2(wp1, wb[j + kw], a1[p][j]);
                a2[p][j] = ffma2(wp2, wb[j + kw], a2[p][j]);
            }
        }
    }
}

// ---- pad kernels -----------------------------------------------------------
static __device__ __forceinline__ void pad_impl(
    const float* __restrict__ src, float* __restrict__ dst, int total)
{
    int g = blockIdx.x * blockDim.x + threadIdx.x;
    if (g >= total) return;
    int fm  = g % FP;
    int row = g / FP;
    int f = fm - 2;
    float v = 0.0f;
    if (f >= 0 && f < F) v = __ldg(src + (size_t)row * F + f);
    dst[g] = v;
}

__global__ void pad_x_kernel(const float* __restrict__ src) {
    pad_impl(src, g_xpad, B * CIX * T * FP);
}
__global__ void pad_h_kernel(const float* __restrict__ src) {
    pad_impl(src, g_hpad, B * C * T * FP);
}

// ---- thread index decomposition shared by main kernels ---------------------
struct Coord { int b, cog, t, fb; };
static __device__ __forceinline__ bool decomp(Coord& c) {
    int g = blockIdx.x * blockDim.x + threadIdx.x;
    if (g >= NTHREAD_MAIN) return false;
    c.fb = g % FBLK;
    int r1 = g / FBLK;
    c.t  = r1 % T;
    int r2 = r1 / T;
    c.cog = r2 & 1;
    c.b   = r2 >> 1;
    return true;
}

// ---- K1: xp = elu(conv(x, pre)) --------------------------------------------
__global__ void __launch_bounds__(256) k1_pre() {
    Coord cc;
    if (!decomp(cc)) return;
    const int f0 = cc.fb * 4, co0 = cc.cog * 4;

    ULL acc[2][4];
#pragma unroll
    for (int p = 0; p < 2; ++p) {
        ULL bb = pk(c_pre_b[co0 + 2 * p], c_pre_b[co0 + 2 * p + 1]);
#pragma unroll
        for (int j = 0; j < 4; ++j) acc[p][j] = bb;
    }

#pragma unroll
    for (int ci = 0; ci < CIX; ++ci) {
        const float* base = g_xpad + (size_t)(cc.b * CIX + ci) * T * FP;
        const float* w    = c_pre_w + (co0 * CIX + ci) * 10;
#pragma unroll
        for (int kh = 0; kh < 2; ++kh) {
            int row = cc.t - 1 + kh;
            if (row < 0) continue;
            conv_row_single(base + (size_t)row * FP + f0, w + kh * 5, CIX * 10, acc);
        }
    }

    // epilogue: elu + masked store into padded g_xp
#pragma unroll
    for (int p = 0; p < 2; ++p) {
        float* rowA = g_xp + ((size_t)(cc.b * C + co0 + 2 * p) * T + cc.t) * FP + 2 + f0;
        float* rowB = g_xp + ((size_t)(cc.b * C + co0 + 2 * p + 1) * T + cc.t) * FP + 2 + f0;
#pragma unroll
        for (int j = 0; j < 4; ++j) {
            float lo, hi;
            upk(acc[p][j], lo, hi);
            lo = lo > 0.0f ? lo : expm1f(lo);
            hi = hi > 0.0f ? hi : expm1f(hi);
            bool valid = (f0 + j) < F;
            rowA[j] = valid ? lo : 0.0f;
            rowB[j] = valid ? hi : 0.0f;
        }
        if (cc.fb == 0) {  // f_mem 0,1
            rowA[-2] = 0.0f; rowA[-1] = 0.0f;
            rowB[-2] = 0.0f; rowB[-1] = 0.0f;
        }
        if (cc.fb == FBLK - 1) {  // f_mem 262..271
#pragma unroll
            for (int q = 4; q < 14; ++q) { rowA[q] = 0.0f; rowB[q] = 0.0f; }
        }
    }
}

// ---- K2: z and rh ----------------------------------------------------------
__global__ void __launch_bounds__(256) k2_zr() {
    Coord cc;
    if (!decomp(cc)) return;
    const int f0 = cc.fb * 4, co0 = cc.cog * 4;

    ULL az[2][4], ar[2][4];
#pragma unroll
    for (int p = 0; p < 2; ++p) {
        int cA = co0 + 2 * p, cB = cA + 1;
        ULL bz = pk(c_xz_b[cA] + c_hz_b[cA], c_xz_b[cB] + c_hz_b[cB]);
        ULL br = pk(c_xr_b[cA] + c_hr_b[cA], c_xr_b[cB] + c_hr_b[cB]);
#pragma unroll
        for (int j = 0; j < 4; ++j) { az[p][j] = bz; ar[p][j] = br; }
    }

#pragma unroll 1
    for (int ci = 0; ci < C; ++ci) {
        const float* xpb = g_xp   + (size_t)(cc.b * C + ci) * T * FP;
        const float* hb  = g_hpad + (size_t)(cc.b * C + ci) * T * FP;
        const int woff = (co0 * C + ci) * 10;
#pragma unroll
        for (int kh = 0; kh < 2; ++kh) {
            int row = cc.t - 1 + kh;
            if (row < 0) continue;
            const size_t ro = (size_t)row * FP + f0;
            conv_row_dual(xpb + ro, c_xz_w + woff + kh * 5, c_xr_w + woff + kh * 5, az, ar);
            conv_row_dual(hb  + ro, c_hz_w + woff + kh * 5, c_hr_w + woff + kh * 5, az, ar);
        }
    }

    float zs[4][4], rs[4][4];
#pragma unroll
    for (int p = 0; p < 2; ++p) {
#pragma unroll
        for (int j = 0; j < 4; ++j) {
            float lo, hi;
            upk(az[p][j], lo, hi);
            zs[2 * p][j] = sigf(lo); zs[2 * p + 1][j] = sigf(hi);
            upk(ar[p][j], lo, hi);
            rs[2 * p][j] = sigf(lo); rs[2 * p + 1][j] = sigf(hi);
        }
    }

#pragma unroll
    for (int cl = 0; cl < 4; ++cl) {
        const int co = co0 + cl;
        const size_t ro = ((size_t)(cc.b * C + co) * T + cc.t) * FP + 2 + f0;
        const float* hrow = g_hpad + ro;
        float* zrow  = g_z  + ro;
        float* rhrow = g_rh + ro;
#pragma unroll
        for (int j = 0; j < 4; ++j) {
            bool valid = (f0 + j) < F;
            float hv = hrow[j];  // 0 in pad region
            zrow[j]  = valid ? zs[cl][j] : 0.0f;
            rhrow[j] = valid ? rs[cl][j] * hv : 0.0f;
        }
        if (cc.fb == 0) {
            zrow[-2] = 0.0f; zrow[-1] = 0.0f;
            rhrow[-2] = 0.0f; rhrow[-1] = 0.0f;
        }
        if (cc.fb == FBLK - 1) {
#pragma unroll
            for (int q = 4; q < 14; ++q) { zrow[q] = 0.0f; rhrow[q] = 0.0f; }
        }
    }
}

// ---- K3: n + output --------------------------------------------------------
__global__ void __launch_bounds__(256) k3_out(float* __restrict__ out) {
    Coord cc;
    if (!decomp(cc)) return;
    const int f0 = cc.fb * 4, co0 = cc.cog * 4;

    ULL an[2][4];
#pragma unroll
    for (int p = 0; p < 2; ++p) {
        int cA = co0 + 2 * p, cB = cA + 1;
        ULL bn = pk(c_xn_b[cA] + c_hn_b[cA], c_xn_b[cB] + c_hn_b[cB]);
#pragma unroll
        for (int j = 0; j < 4; ++j) an[p][j] = bn;
    }

#pragma unroll 1
    for (int ci = 0; ci < C; ++ci) {
        const float* xpb = g_xp + (size_t)(cc.b * C + ci) * T * FP;
        const float* rhb = g_rh + (size_t)(cc.b * C + ci) * T * FP;
        const int woff = (co0 * C + ci) * 10;
#pragma unroll
        for (int kh = 0; kh < 2; ++kh) {
            int row = cc.t - 1 + kh;
            if (row < 0) continue;
            const size_t ro = (size_t)row * FP + f0;
            conv_row_single(xpb + ro, c_xn_w + woff + kh * 5, 80, an);
            conv_row_single(rhb + ro, c_hn_w + woff + kh * 5, 80, an);
        }
    }

    float ns[4][4];
#pragma unroll
    for (int p = 0; p < 2; ++p) {
#pragma unroll
        for (int j = 0; j < 4; ++j) {
            float lo, hi;
            upk(an[p][j], lo, hi);
            ns[2 * p][j] = tanhf(lo);
            ns[2 * p + 1][j] = tanhf(hi);
        }
    }

#pragma unroll
    for (int cl = 0; cl < 4; ++cl) {
        const int co = co0 + cl;
        const size_t ro = ((size_t)(cc.b * C + co) * T + cc.t) * FP + 2 + f0;
        const float* zrow = g_z + ro;
        const float* hrow = g_hpad + ro;
        float* orow = out + ((size_t)(cc.b * C + co) * T + cc.t) * F + f0;
#pragma unroll
        for (int j = 0; j < 4; ++j) {
            if (f0 + j < F) {
                float zz = zrow[j];
                float hv = hrow[j];
                orow[j] = (1.0f - zz) * hv + zz * ns[cl][j];
            }
        }
    }
}

// ---------------------------------------------------------------------------
extern "C" void kernel_launch(void* const* d_in, const int* in_sizes, int n_in,
                              void* d_out, int out_size)
{
    (void)in_sizes; (void)n_in; (void)out_size;
    const float* x = (const float*)d_in[0];
    const float* h = (const float*)d_in[1];

    // weights -> constant memory (graph-capturable D2D memcpys)
    cudaMemcpyToSymbolAsync(c_pre_w, d_in[2],  320 * sizeof(float), 0, cudaMemcpyDeviceToDevice, 0);
    cudaMemcpyToSymbolAsync(c_pre_b, d_in[3],    8 * sizeof(float), 0, cudaMemcpyDeviceToDevice, 0);
    cudaMemcpyToSymbolAsync(c_xz_w,  d_in[4],  640 * sizeof(float), 0, cudaMemcpyDeviceToDevice, 0);
    cudaMemcpyToSymbolAsync(c_xz_b,  d_in[5],    8 * sizeof(float), 0, cudaMemcpyDeviceToDevice, 0);
    cudaMemcpyToSymbolAsync(c_xr_w,  d_in[6],  640 * sizeof(float), 0, cudaMemcpyDeviceToDevice, 0);
    cudaMemcpyToSymbolAsync(c_xr_b,  d_in[7],    8 * sizeof(float), 0, cudaMemcpyDeviceToDevice, 0);
    cudaMemcpyToSymbolAsync(c_xn_w,  d_in[8],  640 * sizeof(float), 0, cudaMemcpyDeviceToDevice, 0);
    cudaMemcpyToSymbolAsync(c_xn_b,  d_in[9],    8 * sizeof(float), 0, cudaMemcpyDeviceToDevice, 0);
    cudaMemcpyToSymbolAsync(c_hz_w,  d_in[10], 640 * sizeof(float), 0, cudaMemcpyDeviceToDevice, 0);
    cudaMemcpyToSymbolAsync(c_hz_b,  d_in[11],   8 * sizeof(float), 0, cudaMemcpyDeviceToDevice, 0);
    cudaMemcpyToSymbolAsync(c_hr_w,  d_in[12], 640 * sizeof(float), 0, cudaMemcpyDeviceToDevice, 0);
    cudaMemcpyToSymbolAsync(c_hr_b,  d_in[13],   8 * sizeof(float), 0, cudaMemcpyDeviceToDevice, 0);
    cudaMemcpyToSymbolAsync(c_hn_w,  d_in[14], 640 * sizeof(float), 0, cudaMemcpyDeviceToDevice, 0);
    cudaMemcpyToSymbolAsync(c_hn_b,  d_in[15],   8 * sizeof(float), 0, cudaMemcpyDeviceToDevice, 0);

    const int BLK = 256;
    {
        int tot = B * CIX * T * FP;
        pad_x_kernel<<<(tot + BLK - 1) / BLK, BLK>>>(x);
    }
    {
        int tot = B * C * T * FP;
        pad_h_kernel<<<(tot + BLK - 1) / BLK, BLK>>>(h);
    }
    const int gmain = (NTHREAD_MAIN + BLK - 1) / BLK;
    k1_pre<<<gmain, BLK>>>();
    k2_zr<<<gmain, BLK>>>();
    k3_out<<<gmain, BLK>>>((float*)d_out);
}

// round 2
// speedup vs baseline: 1.8391x; 1.8391x over previous
#include <cuda_runtime.h>
#include <math.h>

// ---------------------------------------------------------------------------
// MiniStageGRU on GB300 (sm_103a). Conv-GRU without time recursion:
// all convs (2,5), pad H(1,0) W(2,2). B=16, Cin_x=4, C=8, T=1000, F=257.
//
// Round-2 structure:
//  - prep_pack: pack all weights into f32x2 co-pairs {w[2p],w[2p+1]} in a
//    __device__ scratch (biases pre-summed). One-time tiny kernel.
//  - Main kernels tile 8co x 4f per thread. Weight indices are thread-uniform;
//    each block stages packed weights in SMEM and reads them via LDS.128.
//  - Math is fma.rn.f32x2 over co-pairs; the only per-row ALU packing left is
//    8 input broadcast pairs, amortized over 8 co-pairs (and 2 convs in k2).
// ---------------------------------------------------------------------------

typedef unsigned long long ULL;

static __device__ __forceinline__ ULL pk(float lo, float hi) {
    ULL r;
    asm("mov.b64 %0, {%1,%2};" : "=l"(r) : "f"(lo), "f"(hi));
    return r;
}
static __device__ __forceinline__ void upk(ULL v, float& lo, float& hi) {
    asm("mov.b64 {%0,%1}, %2;" : "=f"(lo), "=f"(hi) : "l"(v));
}
static __device__ __forceinline__ ULL ffma2(ULL a, ULL b, ULL c) {
    ULL d;
    asm("fma.rn.f32x2 %0, %1, %2, %3;" : "=l"(d) : "l"(a), "l"(b), "l"(c));
    return d;
}
static __device__ __forceinline__ float sigf(float x) {
    return __fdividef(1.0f, 1.0f + __expf(-x));
}
static __device__ __forceinline__ float tanh_fast(float x) {
    return __fdividef(2.0f, 1.0f + __expf(-2.0f * x)) - 1.0f;
}

constexpr int B    = 16;
constexpr int C    = 8;
constexpr int CIX  = 4;
constexpr int T    = 1000;
constexpr int F    = 257;
constexpr int FP   = 272;   // [2 left pad][257 data][13 right pad]
constexpr int FBLK = 65;    // f tiles of 4

constexpr int NTHREAD_MAIN = B * T * FBLK;   // one thread per (b,t,fblock), all 8 co

// packed-weight scratch layout (ULL units)
// per 8-ci gate: idx = ((ci*2+kh)*5+kw)*4 + p   (p = co pair 0..3), 320 ULL
// pre (4 ci): 160 ULL
constexpr int OFF_PRE  = 0;
constexpr int OFF_XZ   = 160;
constexpr int OFF_XR   = 480;
constexpr int OFF_HZ   = 800;
constexpr int OFF_HR   = 1120;
constexpr int OFF_XN   = 1440;
constexpr int OFF_HN   = 1760;
constexpr int OFF_BPRE = 2080;  // 4 ULL
constexpr int OFF_BZ   = 2084;
constexpr int OFF_BR   = 2088;
constexpr int OFF_BN   = 2092;
constexpr int WPK_N    = 2096;

// ---- device scratch --------------------------------------------------------
__device__ __align__(16) ULL   g_wpk[WPK_N];
__device__ __align__(16) float g_xpad[(size_t)B * CIX * T * FP];
__device__ __align__(16) float g_hpad[(size_t)B * C   * T * FP];
__device__ __align__(16) float g_xp  [(size_t)B * C   * T * FP];
__device__ __align__(16) float g_z   [(size_t)B * C   * T * FP];
__device__ __align__(16) float g_rh  [(size_t)B * C   * T * FP];

// ---- weight packing --------------------------------------------------------
__global__ void prep_pack(const float* __restrict__ pre_w, const float* __restrict__ pre_b,
                          const float* __restrict__ xz_w,  const float* __restrict__ xz_b,
                          const float* __restrict__ xr_w,  const float* __restrict__ xr_b,
                          const float* __restrict__ xn_w,  const float* __restrict__ xn_b,
                          const float* __restrict__ hz_w,  const float* __restrict__ hz_b,
                          const float* __restrict__ hr_w,  const float* __restrict__ hr_b,
                          const float* __restrict__ hn_w,  const float* __restrict__ hn_b)
{
    int i = blockIdx.x * blockDim.x + threadIdx.x;
    if (i >= WPK_N) return;
    ULL v;
    if (i < OFF_XZ) {                      // pre: (8co, 4ci, 2, 5)
        int r = i; int p = r & 3; int q = r >> 2;
        int kw = q % 5; q /= 5; int kh = q & 1; int ci = q >> 1;
        v = pk(pre_w[((2 * p)     * CIX + ci) * 10 + kh * 5 + kw],
               pre_w[((2 * p + 1) * CIX + ci) * 10 + kh * 5 + kw]);
    } else if (i < OFF_BPRE) {             // gate weights: (8co, 8ci, 2, 5)
        int gi = (i - OFF_XZ) / 320;
        int r  = (i - OFF_XZ) % 320;
        int p = r & 3; int q = r >> 2;
        int kw = q % 5; q /= 5; int kh = q & 1; int ci = q >> 1;
        const float* w = (gi == 0) ? xz_w : (gi == 1) ? xr_w : (gi == 2) ? hz_w
                       : (gi == 3) ? hr_w : (gi == 4) ? xn_w : hn_w;
        v = pk(w[((2 * p)     * C + ci) * 10 + kh * 5 + kw],
               w[((2 * p + 1) * C + ci) * 10 + kh * 5 + kw]);
    } else {                               // biases (pre-summed for gates)
        int j = i - OFF_BPRE; int which = j >> 2; int p = j & 3;
        if (which == 0)      v = pk(pre_b[2 * p], pre_b[2 * p + 1]);
        else if (which == 1) v = pk(xz_b[2 * p] + hz_b[2 * p], xz_b[2 * p + 1] + hz_b[2 * p + 1]);
        else if (which == 2) v = pk(xr_b[2 * p] + hr_b[2 * p], xr_b[2 * p + 1] + hr_b[2 * p + 1]);
        else                 v = pk(xn_b[2 * p] + hn_b[2 * p], xn_b[2 * p + 1] + hn_b[2 * p + 1]);
    }
    g_wpk[i] = v;
}

// ---- conv row micro-kernels (weights from SMEM, 4 co-pairs) ----------------
// rowp: padded input row at f_mem = f0. acc[p][j]: pair (co=2p,2p+1), f=f0+j.
// w: &sw[OFF_gate + (ci*2+kh)*20]  (20 = 5kw * 4p, 16B-aligned groups)
static __device__ __forceinline__ void conv_row(
    const float* __restrict__ rowp, const ULL* __restrict__ w, ULL acc[4][4])
{
    float4 A  = *reinterpret_cast<const float4*>(rowp);
    float4 Bv = *reinterpret_cast<const float4*>(rowp + 4);
    float win[8] = {A.x, A.y, A.z, A.w, Bv.x, Bv.y, Bv.z, Bv.w};
    ULL wb[8];
#pragma unroll
    for (int m = 0; m < 8; ++m) wb[m] = pk(win[m], win[m]);
#pragma unroll
    for (int kw = 0; kw < 5; ++kw) {
        ulonglong2 w01 = *reinterpret_cast<const ulonglong2*>(w + kw * 4);
        ulonglong2 w23 = *reinterpret_cast<const ulonglong2*>(w + kw * 4 + 2);
#pragma unroll
        for (int j = 0; j < 4; ++j) {
            acc[0][j] = ffma2(w01.x, wb[j + kw], acc[0][j]);
            acc[1][j] = ffma2(w01.y, wb[j + kw], acc[1][j]);
            acc[2][j] = ffma2(w23.x, wb[j + kw], acc[2][j]);
            acc[3][j] = ffma2(w23.y, wb[j + kw], acc[3][j]);
        }
    }
}

// two convolutions over the same input row (shared broadcast packs)
static __device__ __forceinline__ void conv_row_dual(
    const float* __restrict__ rowp,
    const ULL* __restrict__ w1, const ULL* __restrict__ w2,
    ULL a1[4][4], ULL a2[4][4])
{
    float4 A  = *reinterpret_cast<const float4*>(rowp);
    float4 Bv = *reinterpret_cast<const float4*>(rowp + 4);
    float win[8] = {A.x, A.y, A.z, A.w, Bv.x, Bv.y, Bv.z, Bv.w};
    ULL wb[8];
#pragma unroll
    for (int m = 0; m < 8; ++m) wb[m] = pk(win[m], win[m]);
#pragma unroll
    for (int kw = 0; kw < 5; ++kw) {
        ulonglong2 u01 = *reinterpret_cast<const ulonglong2*>(w1 + kw * 4);
        ulonglong2 u23 = *reinterpret_cast<const ulonglong2*>(w1 + kw * 4 + 2);
        ulonglong2 v01 = *reinterpret_cast<const ulonglong2*>(w2 + kw * 4);
        ulonglong2 v23 = *reinterpret_cast<const ulonglong2*>(w2 + kw * 4 + 2);
#pragma unroll
        for (int j = 0; j < 4; ++j) {
            a1[0][j] = ffma2(u01.x, wb[j + kw], a1[0][j]);
            a1[1][j] = ffma2(u01.y, wb[j + kw], a1[1][j]);
            a1[2][j] = ffma2(u23.x, wb[j + kw], a1[2][j]);
            a1[3][j] = ffma2(u23.y, wb[j + kw], a1[3][j]);
            a2[0][j] = ffma2(v01.x, wb[j + kw], a2[0][j]);
            a2[1][j] = ffma2(v01.y, wb[j + kw], a2[1][j]);
            a2[2][j] = ffma2(v23.x, wb[j + kw], a2[2][j]);
            a2[3][j] = ffma2(v23.y, wb[j + kw], a2[3][j]);
        }
    }
}

// ---- pad kernels -----------------------------------------------------------
static __device__ __forceinline__ void pad_impl(
    const float* __restrict__ src, float* __restrict__ dst, int total)
{
    int g = blockIdx.x * blockDim.x + threadIdx.x;
    if (g >= total) return;
    int fm  = g % FP;
    int row = g / FP;
    int f = fm - 2;
    float v = 0.0f;
    if (f >= 0 && f < F) v = __ldg(src + (size_t)row * F + f);
    dst[g] = v;
}
__global__ void pad_x_kernel(const float* __restrict__ src) {
    pad_impl(src, g_xpad, B * CIX * T * FP);
}
__global__ void pad_h_kernel(const float* __restrict__ src) {
    pad_impl(src, g_hpad, B * C * T * FP);
}

// ---- shared-weight staging (all threads, before any early return) ----------
#define STAGE_WEIGHTS()                                            \
    __shared__ __align__(16) ULL sw[WPK_N];                        \
    for (int i = threadIdx.x; i < WPK_N; i += 256) sw[i] = g_wpk[i]; \
    __syncthreads();

// ---- K1: xp = elu(conv(x, pre)) --------------------------------------------
__global__ void __launch_bounds__(256) k1_pre() {
    STAGE_WEIGHTS();
    int g = blockIdx.x * 256 + threadIdx.x;
    if (g >= NTHREAD_MAIN) return;
    const int fb = g % FBLK; int r1 = g / FBLK;
    const int t = r1 % T, b = r1 / T;
    const int f0 = fb * 4;

    ULL acc[4][4];
#pragma unroll
    for (int p = 0; p < 4; ++p) {
        ULL bb = sw[OFF_BPRE + p];
#pragma unroll
        for (int j = 0; j < 4; ++j) acc[p][j] = bb;
    }

#pragma unroll
    for (int ci = 0; ci < CIX; ++ci) {
        const float* base = g_xpad + (size_t)(b * CIX + ci) * T * FP;
#pragma unroll
        for (int kh = 0; kh < 2; ++kh) {
            int row = t - 1 + kh;
            if (row < 0) continue;
            conv_row(base + (size_t)row * FP + f0, sw + OFF_PRE + ci * 40 + kh * 20, acc);
        }
    }

#pragma unroll
    for (int p = 0; p < 4; ++p) {
        float* rowA = g_xp + ((size_t)(b * C + 2 * p)     * T + t) * FP + 2 + f0;
        float* rowB = g_xp + ((size_t)(b * C + 2 * p + 1) * T + t) * FP + 2 + f0;
#pragma unroll
        for (int j = 0; j < 4; ++j) {
            float lo, hi;
            upk(acc[p][j], lo, hi);
            lo = lo > 0.0f ? lo : expm1f(lo);
            hi = hi > 0.0f ? hi : expm1f(hi);
            bool valid = (f0 + j) < F;
            rowA[j] = valid ? lo : 0.0f;
            rowB[j] = valid ? hi : 0.0f;
        }
        if (fb == 0) { rowA[-2] = rowA[-1] = 0.0f; rowB[-2] = rowB[-1] = 0.0f; }
        if (fb == FBLK - 1) {
#pragma unroll
            for (int q = 4; q < 14; ++q) { rowA[q] = 0.0f; rowB[q] = 0.0f; }
        }
    }
}

// ---- K2: z and r*h ----------------------------------------------------------
__global__ void __launch_bounds__(256) k2_zr() {
    STAGE_WEIGHTS();
    int g = blockIdx.x * 256 + threadIdx.x;
    if (g >= NTHREAD_MAIN) return;
    const int fb = g % FBLK; int r1 = g / FBLK;
    const int t = r1 % T, b = r1 / T;
    const int f0 = fb * 4;

    ULL az[4][4], ar[4][4];
#pragma unroll
    for (int p = 0; p < 4; ++p) {
        ULL bz = sw[OFF_BZ + p], br = sw[OFF_BR + p];
#pragma unroll
        for (int j = 0; j < 4; ++j) { az[p][j] = bz; ar[p][j] = br; }
    }

#pragma unroll 1
    for (int ci = 0; ci < C; ++ci) {
        const float* xpb = g_xp   + (size_t)(b * C + ci) * T * FP;
        const float* hb  = g_hpad + (size_t)(b * C + ci) * T * FP;
        const int wo = ci * 40;
#pragma unroll
        for (int kh = 0; kh < 2; ++kh) {
            int row = t - 1 + kh;
            if (row < 0) continue;
            const size_t ro = (size_t)row * FP + f0;
            conv_row_dual(xpb + ro, sw + OFF_XZ + wo + kh * 20, sw + OFF_XR + wo + kh * 20, az, ar);
            conv_row_dual(hb  + ro, sw + OFF_HZ + wo + kh * 20, sw + OFF_HR + wo + kh * 20, az, ar);
        }
    }

#pragma unroll
    for (int p = 0; p < 4; ++p) {
        float zlo[4], zhi[4], rlo[4], rhi[4];
#pragma unroll
        for (int j = 0; j < 4; ++j) {
            float a, bb;
            upk(az[p][j], a, bb); zlo[j] = sigf(a); zhi[j] = sigf(bb);
            upk(ar[p][j], a, bb); rlo[j] = sigf(a); rhi[j] = sigf(bb);
        }
#pragma unroll
        for (int half = 0; half < 2; ++half) {
            const int co = 2 * p + half;
            const float* zz = half ? zhi : zlo;
            const float* rr = half ? rhi : rlo;
            const size_t ro = ((size_t)(b * C + co) * T + t) * FP + 2 + f0;
            const float* hrow = g_hpad + ro;
            float* zrow  = g_z  + ro;
            float* rhrow = g_rh + ro;
#pragma unroll
            for (int j = 0; j < 4; ++j) {
                bool valid = (f0 + j) < F;
                float hv = hrow[j];
                zrow[j]  = valid ? zz[j] : 0.0f;
                rhrow[j] = valid ? rr[j] * hv : 0.0f;
            }
            if (fb == 0) { zrow[-2] = zrow[-1] = 0.0f; rhrow[-2] = rhrow[-1] = 0.0f; }
            if (fb == FBLK - 1) {
#pragma unroll
                for (int q = 4; q < 14; ++q) { zrow[q] = 0.0f; rhrow[q] = 0.0f; }
            }
        }
    }
}

// ---- K3: n + output ----------------------------------------------------------
__global__ void __launch_bounds__(256) k3_out(float* __restrict__ out) {
    STAGE_WEIGHTS();
    int g = blockIdx.x * 256 + threadIdx.x;
    if (g >= NTHREAD_MAIN) return;
    const int fb = g % FBLK; int r1 = g / FBLK;
    const int t = r1 % T, b = r1 / T;
    const int f0 = fb * 4;

    ULL an[4][4];
#pragma unroll
    for (int p = 0; p < 4; ++p) {
        ULL bn = sw[OFF_BN + p];
#pragma unroll
        for (int j = 0; j < 4; ++j) an[p][j] = bn;
    }

#pragma unroll 1
    for (int ci = 0; ci < C; ++ci) {
        const float* xpb = g_xp + (size_t)(b * C + ci) * T * FP;
        const float* rhb = g_rh + (size_t)(b * C + ci) * T * FP;
        const int wo = ci * 40;
#pragma unroll
        for (int kh = 0; kh < 2; ++kh) {
            int row = t - 1 + kh;
            if (row < 0) continue;
            const size_t ro = (size_t)row * FP + f0;
            conv_row(xpb + ro, sw + OFF_XN + wo + kh * 20, an);
            conv_row(rhb + ro, sw + OFF_HN + wo + kh * 20, an);
        }
    }

#pragma unroll
    for (int p = 0; p < 4; ++p) {
        float nlo[4], nhi[4];
#pragma unroll
        for (int j = 0; j < 4; ++j) {
            float a, bb;
            upk(an[p][j], a, bb);
            nlo[j] = tanh_fast(a); nhi[j] = tanh_fast(bb);
        }
#pragma unroll
        for (int half = 0; half < 2; ++half) {
            const int co = 2 * p + half;
            const float* nn = half ? nhi : nlo;
            const size_t ro = ((size_t)(b * C + co) * T + t) * FP + 2 + f0;
            const float* zrow = g_z + ro;
            const float* hrow = g_hpad + ro;
            float* orow = out + ((size_t)(b * C + co) * T + t) * F + f0;
#pragma unroll
            for (int j = 0; j < 4; ++j) {
                if (f0 + j < F) {
                    float zz = zrow[j];
                    float hv = hrow[j];
                    orow[j] = (1.0f - zz) * hv + zz * nn[j];
                }
            }
        }
    }
}

// ---------------------------------------------------------------------------
extern "C" void kernel_launch(void* const* d_in, const int* in_sizes, int n_in,
                              void* d_out, int out_size)
{
    (void)in_sizes; (void)n_in; (void)out_size;
    const float* x = (const float*)d_in[0];
    const float* h = (const float*)d_in[1];

    prep_pack<<<(WPK_N + 255) / 256, 256>>>(
        (const float*)d_in[2],  (const float*)d_in[3],
        (const float*)d_in[4],  (const float*)d_in[5],
        (const float*)d_in[6],  (const float*)d_in[7],
        (const float*)d_in[8],  (const float*)d_in[9],
        (const float*)d_in[10], (const float*)d_in[11],
        (const float*)d_in[12], (const float*)d_in[13],
        (const float*)d_in[14], (const float*)d_in[15]);

    const int BLK = 256;
    {
        int tot = B * CIX * T * FP;
        pad_x_kernel<<<(tot + BLK - 1) / BLK, BLK>>>(x);
    }
    {
        int tot = B * C * T * FP;
        pad_h_kernel<<<(tot + BLK - 1) / BLK, BLK>>>(h);
    }
    const int gmain = (NTHREAD_MAIN + BLK - 1) / BLK;
    k1_pre<<<gmain, BLK>>>();
    k2_zr<<<gmain, BLK>>>();
    k3_out<<<gmain, BLK>>>((float*)d_out);
}

// round 3
// speedup vs baseline: 2.1603x; 1.1747x over previous
#include <cuda_runtime.h>
#include <math.h>

// ---------------------------------------------------------------------------
// MiniStageGRU on GB300 (sm_103a). Conv-GRU, convs (2,5), pad H(1,0) W(2,2).
// B=16, Cin_x=4, C=8, T=1000, F=257.
//
// Round-3:
//  - [T+1]-row padded layouts with zero row 0 -> branch-free conv rows (t+kh).
//  - 32-bit incremental addressing.
//  - #pragma unroll 2 on ci loops for cross-site load prefetch.
//  - float2-vectorized epilogues and pad kernels.
// Weights: pre-packed f32x2 co-pairs in __device__ scratch, staged to SMEM.
// ---------------------------------------------------------------------------

typedef unsigned long long ULL;

static __device__ __forceinline__ ULL pk(float lo, float hi) {
    ULL r;
    asm("mov.b64 %0, {%1,%2};" : "=l"(r) : "f"(lo), "f"(hi));
    return r;
}
static __device__ __forceinline__ void upk(ULL v, float& lo, float& hi) {
    asm("mov.b64 {%0,%1}, %2;" : "=f"(lo), "=f"(hi) : "l"(v));
}
static __device__ __forceinline__ ULL ffma2(ULL a, ULL b, ULL c) {
    ULL d;
    asm("fma.rn.f32x2 %0, %1, %2, %3;" : "=l"(d) : "l"(a), "l"(b), "l"(c));
    return d;
}
static __device__ __forceinline__ float sigf(float x) {
    return __fdividef(1.0f, 1.0f + __expf(-x));
}
static __device__ __forceinline__ float tanh_fast(float x) {
    return __fdividef(2.0f, 1.0f + __expf(-2.0f * x)) - 1.0f;
}

constexpr int B    = 16;
constexpr int C    = 8;
constexpr int CIX  = 4;
constexpr int T    = 1000;
constexpr int TP1  = 1001;          // T+1 rows, row 0 = zeros
constexpr int F    = 257;
constexpr int FP   = 272;           // [2 left pad][257 data][13 right pad]
constexpr int CH   = TP1 * FP;      // 272272 floats per channel
constexpr int FBLK = 65;

constexpr int NTHREAD_MAIN = B * T * FBLK;

// packed-weight scratch layout (ULL units): idx = OFF + (ci*2+kh)*20 + kw*4 + p
constexpr int OFF_PRE  = 0;
constexpr int OFF_XZ   = 160;
constexpr int OFF_XR   = 480;
constexpr int OFF_HZ   = 800;
constexpr int OFF_HR   = 1120;
constexpr int OFF_XN   = 1440;
constexpr int OFF_HN   = 1760;
constexpr int OFF_BPRE = 2080;
constexpr int OFF_BZ   = 2084;
constexpr int OFF_BR   = 2088;
constexpr int OFF_BN   = 2092;
constexpr int WPK_N    = 2096;

// ---- device scratch --------------------------------------------------------
__device__ __align__(16) ULL   g_wpk[WPK_N];
__device__ __align__(16) float g_xpad[(size_t)B * CIX * CH];
__device__ __align__(16) float g_hpad[(size_t)B * C   * CH];
__device__ __align__(16) float g_xp  [(size_t)B * C   * CH];
__device__ __align__(16) float g_z   [(size_t)B * C   * CH];
__device__ __align__(16) float g_rh  [(size_t)B * C   * CH];

// ---- weight packing --------------------------------------------------------
__global__ void prep_pack(const float* __restrict__ pre_w, const float* __restrict__ pre_b,
                          const float* __restrict__ xz_w,  const float* __restrict__ xz_b,
                          const float* __restrict__ xr_w,  const float* __restrict__ xr_b,
                          const float* __restrict__ xn_w,  const float* __restrict__ xn_b,
                          const float* __restrict__ hz_w,  const float* __restrict__ hz_b,
                          const float* __restrict__ hr_w,  const float* __restrict__ hr_b,
                          const float* __restrict__ hn_w,  const float* __restrict__ hn_b)
{
    int i = blockIdx.x * blockDim.x + threadIdx.x;
    if (i >= WPK_N) return;
    ULL v;
    if (i < OFF_XZ) {                      // pre: (8co, 4ci, 2, 5)
        int r = i; int p = r & 3; int q = r >> 2;
        int kw = q % 5; q /= 5; int kh = q & 1; int ci = q >> 1;
        v = pk(pre_w[((2 * p)     * CIX + ci) * 10 + kh * 5 + kw],
               pre_w[((2 * p + 1) * CIX + ci) * 10 + kh * 5 + kw]);
    } else if (i < OFF_BPRE) {             // gate weights: (8co, 8ci, 2, 5)
        int gi = (i - OFF_XZ) / 320;
        int r  = (i - OFF_XZ) % 320;
        int p = r & 3; int q = r >> 2;
        int kw = q % 5; q /= 5; int kh = q & 1; int ci = q >> 1;
        const float* w = (gi == 0) ? xz_w : (gi == 1) ? xr_w : (gi == 2) ? hz_w
                       : (gi == 3) ? hr_w : (gi == 4) ? xn_w : hn_w;
        v = pk(w[((2 * p)     * C + ci) * 10 + kh * 5 + kw],
               w[((2 * p + 1) * C + ci) * 10 + kh * 5 + kw]);
    } else {
        int j = i - OFF_BPRE; int which = j >> 2; int p = j & 3;
        if (which == 0)      v = pk(pre_b[2 * p], pre_b[2 * p + 1]);
        else if (which == 1) v = pk(xz_b[2 * p] + hz_b[2 * p], xz_b[2 * p + 1] + hz_b[2 * p + 1]);
        else if (which == 2) v = pk(xr_b[2 * p] + hr_b[2 * p], xr_b[2 * p + 1] + hr_b[2 * p + 1]);
        else                 v = pk(xn_b[2 * p] + hn_b[2 * p], xn_b[2 * p + 1] + hn_b[2 * p + 1]);
    }
    g_wpk[i] = v;
}

// ---- conv row micro-kernels -------------------------------------------------
static __device__ __forceinline__ void conv_row(
    const float* __restrict__ rowp, const ULL* __restrict__ w, ULL acc[4][4])
{
    float4 A  = *reinterpret_cast<const float4*>(rowp);
    float4 Bv = *reinterpret_cast<const float4*>(rowp + 4);
    float win[8] = {A.x, A.y, A.z, A.w, Bv.x, Bv.y, Bv.z, Bv.w};
    ULL wb[8];
#pragma unroll
    for (int m = 0; m < 8; ++m) wb[m] = pk(win[m], win[m]);
#pragma unroll
    for (int kw = 0; kw < 5; ++kw) {
        ulonglong2 w01 = *reinterpret_cast<const ulonglong2*>(w + kw * 4);
        ulonglong2 w23 = *reinterpret_cast<const ulonglong2*>(w + kw * 4 + 2);
#pragma unroll
        for (int j = 0; j < 4; ++j) {
            acc[0][j] = ffma2(w01.x, wb[j + kw], acc[0][j]);
            acc[1][j] = ffma2(w01.y, wb[j + kw], acc[1][j]);
            acc[2][j] = ffma2(w23.x, wb[j + kw], acc[2][j]);
            acc[3][j] = ffma2(w23.y, wb[j + kw], acc[3][j]);
        }
    }
}

static __device__ __forceinline__ void conv_row_dual(
    const float* __restrict__ rowp,
    const ULL* __restrict__ w1, const ULL* __restrict__ w2,
    ULL a1[4][4], ULL a2[4][4])
{
    float4 A  = *reinterpret_cast<const float4*>(rowp);
    float4 Bv = *reinterpret_cast<const float4*>(rowp + 4);
    float win[8] = {A.x, A.y, A.z, A.w, Bv.x, Bv.y, Bv.z, Bv.w};
    ULL wb[8];
#pragma unroll
    for (int m = 0; m < 8; ++m) wb[m] = pk(win[m], win[m]);
#pragma unroll
    for (int kw = 0; kw < 5; ++kw) {
        ulonglong2 u01 = *reinterpret_cast<const ulonglong2*>(w1 + kw * 4);
        ulonglong2 u23 = *reinterpret_cast<const ulonglong2*>(w1 + kw * 4 + 2);
        ulonglong2 v01 = *reinterpret_cast<const ulonglong2*>(w2 + kw * 4);
        ulonglong2 v23 = *reinterpret_cast<const ulonglong2*>(w2 + kw * 4 + 2);
#pragma unroll
        for (int j = 0; j < 4; ++j) {
            a1[0][j] = ffma2(u01.x, wb[j + kw], a1[0][j]);
            a1[1][j] = ffma2(u01.y, wb[j + kw], a1[1][j]);
            a1[2][j] = ffma2(u23.x, wb[j + kw], a1[2][j]);
            a1[3][j] = ffma2(u23.y, wb[j + kw], a1[3][j]);
            a2[0][j] = ffma2(v01.x, wb[j + kw], a2[0][j]);
            a2[1][j] = ffma2(v01.y, wb[j + kw], a2[1][j]);
            a2[2][j] = ffma2(v23.x, wb[j + kw], a2[2][j]);
            a2[3][j] = ffma2(v23.y, wb[j + kw], a2[3][j]);
        }
    }
}

// ---- pad kernels: src [BC][T][F] -> dst [BC][TP1][FP], row0/edges zero ------
static __device__ __forceinline__ void pad_impl(
    const float* __restrict__ src, float* __restrict__ dst, int total_pairs)
{
    int g = blockIdx.x * blockDim.x + threadIdx.x;
    if (g >= total_pairs) return;
    int e0 = g * 2;
    int fm = e0 % FP;
    int r  = e0 / FP;
    int tr = r % TP1;
    int bc = r / TP1;
    float2 v = make_float2(0.0f, 0.0f);
    if (tr > 0) {
        const float* srow = src + (bc * T + tr - 1) * F;
        int f0 = fm - 2;
        if (f0 >= 0 && f0 < F)     v.x = srow[f0];
        if (f0 + 1 >= 0 && f0 + 1 < F) v.y = srow[f0 + 1];
    }
    *reinterpret_cast<float2*>(dst + e0) = v;
}
__global__ void pad_x_kernel(const float* __restrict__ src) {
    pad_impl(src, g_xpad, B * CIX * CH / 2);
}
__global__ void pad_h_kernel(const float* __restrict__ src) {
    pad_impl(src, g_hpad, B * C * CH / 2);
}

// zero row 0 of g_xp and g_rh
__global__ void zero_rows() {
    int g = blockIdx.x * blockDim.x + threadIdx.x;
    int n = B * C * FP;
    if (g >= n) return;
    int fm = g % FP;
    int bc = g / FP;
    g_xp[bc * CH + fm] = 0.0f;
    g_rh[bc * CH + fm] = 0.0f;
}

#define STAGE_WEIGHTS()                                              \
    __shared__ __align__(16) ULL sw[WPK_N];                          \
    for (int i = threadIdx.x; i < WPK_N; i += 256) sw[i] = g_wpk[i]; \
    __syncthreads();

static __device__ __forceinline__ void st2(float* p, float a, float b) {
    *reinterpret_cast<float2*>(p) = make_float2(a, b);
}

// ---- K1: xp = elu(conv(x, pre)) ---------------------------------------------
__global__ void __launch_bounds__(256) k1_pre() {
    STAGE_WEIGHTS();
    int g = blockIdx.x * 256 + threadIdx.x;
    if (g >= NTHREAD_MAIN) return;
    const int fb = g % FBLK; int r1 = g / FBLK;
    const int t = r1 % T, b = r1 / T;
    const int f0 = fb * 4;

    ULL acc[4][4];
#pragma unroll
    for (int p = 0; p < 4; ++p) {
        ULL bb = sw[OFF_BPRE + p];
#pragma unroll
        for (int j = 0; j < 4; ++j) acc[p][j] = bb;
    }

    int o = (b * CIX) * CH + t * FP + f0;  // rows t (=kh0), t+1 (=kh1)
#pragma unroll
    for (int ci = 0; ci < CIX; ++ci) {
        conv_row(g_xpad + o,      sw + OFF_PRE + ci * 40,      acc);
        conv_row(g_xpad + o + FP, sw + OFF_PRE + ci * 40 + 20, acc);
        o += CH;
    }

    const bool lastfb = (fb == FBLK - 1);
#pragma unroll
    for (int p = 0; p < 4; ++p) {
        float* rowA = g_xp + (b * C + 2 * p)     * CH + (t + 1) * FP + 2 + f0;
        float* rowB = g_xp + (b * C + 2 * p + 1) * CH + (t + 1) * FP + 2 + f0;
        float v[2][4];
#pragma unroll
        for (int j = 0; j < 4; ++j) {
            float lo, hi;
            upk(acc[p][j], lo, hi);
            lo = lo > 0.0f ? lo : expm1f(lo);
            hi = hi > 0.0f ? hi : expm1f(hi);
            bool valid = (f0 + j) < F;
            v[0][j] = valid ? lo : 0.0f;
            v[1][j] = valid ? hi : 0.0f;
        }
        st2(rowA,     v[0][0], v[0][1]); st2(rowA + 2, v[0][2], v[0][3]);
        st2(rowB,     v[1][0], v[1][1]); st2(rowB + 2, v[1][2], v[1][3]);
        if (fb == 0) { st2(rowA - 2, 0.f, 0.f); st2(rowB - 2, 0.f, 0.f); }
        if (lastfb) {
#pragma unroll
            for (int q = 4; q < 14; q += 2) { st2(rowA + q, 0.f, 0.f); st2(rowB + q, 0.f, 0.f); }
        }
    }
}

// ---- K2: z and r*h ------------------------------------------------------------
__global__ void __launch_bounds__(256) k2_zr() {
    STAGE_WEIGHTS();
    int g = blockIdx.x * 256 + threadIdx.x;
    if (g >= NTHREAD_MAIN) return;
    const int fb = g % FBLK; int r1 = g / FBLK;
    const int t = r1 % T, b = r1 / T;
    const int f0 = fb * 4;

    ULL az[4][4], ar[4][4];
#pragma unroll
    for (int p = 0; p < 4; ++p) {
        ULL bz = sw[OFF_BZ + p], br = sw[OFF_BR + p];
#pragma unroll
        for (int j = 0; j < 4; ++j) { az[p][j] = bz; ar[p][j] = br; }
    }

    int o = (b * C) * CH + t * FP + f0;
    int wo = 0;
#pragma unroll 2
    for (int ci = 0; ci < C; ++ci) {
        const float* xr = g_xp + o;
        const float* hr = g_hpad + o;
        conv_row_dual(xr,      sw + OFF_XZ + wo,      sw + OFF_XR + wo,      az, ar);
        conv_row_dual(xr + FP, sw + OFF_XZ + wo + 20, sw + OFF_XR + wo + 20, az, ar);
        conv_row_dual(hr,      sw + OFF_HZ + wo,      sw + OFF_HR + wo,      az, ar);
        conv_row_dual(hr + FP, sw + OFF_HZ + wo + 20, sw + OFF_HR + wo + 20, az, ar);
        o += CH; wo += 40;
    }

    const bool lastfb = (fb == FBLK - 1);
#pragma unroll
    for (int p = 0; p < 4; ++p) {
        float zv[2][4], rv[2][4];
#pragma unroll
        for (int j = 0; j < 4; ++j) {
            float a, bb;
            upk(az[p][j], a, bb); zv[0][j] = sigf(a); zv[1][j] = sigf(bb);
            upk(ar[p][j], a, bb); rv[0][j] = sigf(a); rv[1][j] = sigf(bb);
        }
#pragma unroll
        for (int half = 0; half < 2; ++half) {
            const int co = 2 * p + half;
            const int ro = (b * C + co) * CH + (t + 1) * FP + 2 + f0;
            const float* hrow = g_hpad + ro;
            float* zrow  = g_z  + ro;
            float* rhrow = g_rh + ro;
            float z0 = zv[half][0], z1 = zv[half][1], z2 = zv[half][2], z3 = zv[half][3];
            if (lastfb) { z1 = 0.f; z2 = 0.f; z3 = 0.f; }  // f0+j >= F for j>0
            // rh: h pad is 0 beyond F, so no masking needed
            float2 h01 = *reinterpret_cast<const float2*>(hrow);
            float2 h23 = *reinterpret_cast<const float2*>(hrow + 2);
            st2(zrow,      z0, z1);                         st2(zrow + 2,  z2, z3);
            st2(rhrow,     rv[half][0] * h01.x, rv[half][1] * h01.y);
            st2(rhrow + 2, rv[half][2] * h23.x, rv[half][3] * h23.y);
            if (fb == 0) { st2(zrow - 2, 0.f, 0.f); st2(rhrow - 2, 0.f, 0.f); }
            if (lastfb) {
#pragma unroll
                for (int q = 4; q < 14; q += 2) { st2(zrow + q, 0.f, 0.f); st2(rhrow + q, 0.f, 0.f); }
            }
        }
    }
}

// ---- K3: n + output -------------------------------------------------------------
__global__ void __launch_bounds__(256) k3_out(float* __restrict__ out) {
    STAGE_WEIGHTS();
    int g = blockIdx.x * 256 + threadIdx.x;
    if (g >= NTHREAD_MAIN) return;
    const int fb = g % FBLK; int r1 = g / FBLK;
    const int t = r1 % T, b = r1 / T;
    const int f0 = fb * 4;

    ULL an[4][4];
#pragma unroll
    for (int p = 0; p < 4; ++p) {
        ULL bn = sw[OFF_BN + p];
#pragma unroll
        for (int j = 0; j < 4; ++j) an[p][j] = bn;
    }

    int o = (b * C) * CH + t * FP + f0;
    int wo = 0;
#pragma unroll 2
    for (int ci = 0; ci < C; ++ci) {
        const float* xr  = g_xp + o;
        const float* rhr = g_rh + o;
        conv_row(xr,       sw + OFF_XN + wo,      an);
        conv_row(xr + FP,  sw + OFF_XN + wo + 20, an);
        conv_row(rhr,      sw + OFF_HN + wo,      an);
        conv_row(rhr + FP, sw + OFF_HN + wo + 20, an);
        o += CH; wo += 40;
    }

#pragma unroll
    for (int p = 0; p < 4; ++p) {
        float nv[2][4];
#pragma unroll
        for (int j = 0; j < 4; ++j) {
            float a, bb;
            upk(an[p][j], a, bb);
            nv[0][j] = tanh_fast(a); nv[1][j] = tanh_fast(bb);
        }
#pragma unroll
        for (int half = 0; half < 2; ++half) {
            const int co = 2 * p + half;
            const int ro = (b * C + co) * CH + (t + 1) * FP + 2 + f0;
            const float* zrow = g_z + ro;
            const float* hrow = g_hpad + ro;
            float* orow = out + (b * C + co) * (T * F) + t * F + f0;
            float2 z01 = *reinterpret_cast<const float2*>(zrow);
            float2 z23 = *reinterpret_cast<const float2*>(zrow + 2);
            float2 h01 = *reinterpret_cast<const float2*>(hrow);
            float2 h23 = *reinterpret_cast<const float2*>(hrow + 2);
            float zz[4] = {z01.x, z01.y, z23.x, z23.y};
            float hh[4] = {h01.x, h01.y, h23.x, h23.y};
#pragma unroll
            for (int j = 0; j < 4; ++j) {
                if (f0 + j < F)
                    orow[j] = (1.0f - zz[j]) * hh[j] + zz[j] * nv[half][j];
            }
        }
    }
}

// ---------------------------------------------------------------------------
extern "C" void kernel_launch(void* const* d_in, const int* in_sizes, int n_in,
                              void* d_out, int out_size)
{
    (void)in_sizes; (void)n_in; (void)out_size;
    const float* x = (const float*)d_in[0];
    const float* h = (const float*)d_in[1];

    prep_pack<<<(WPK_N + 255) / 256, 256>>>(
        (const float*)d_in[2],  (const float*)d_in[3],
        (const float*)d_in[4],  (const float*)d_in[5],
        (const float*)d_in[6],  (const float*)d_in[7],
        (const float*)d_in[8],  (const float*)d_in[9],
        (const float*)d_in[10], (const float*)d_in[11],
        (const float*)d_in[12], (const float*)d_in[13],
        (const float*)d_in[14], (const float*)d_in[15]);

    const int BLK = 256;
    {
        int pr = B * CIX * CH / 2;
        pad_x_kernel<<<(pr + BLK - 1) / BLK, BLK>>>(x);
    }
    {
        int pr = B * C * CH / 2;
        pad_h_kernel<<<(pr + BLK - 1) / BLK, BLK>>>(h);
    }
    {
        int n = B * C * FP;
        zero_rows<<<(n + BLK - 1) / BLK, BLK>>>();
    }
    const int gmain = (NTHREAD_MAIN + BLK - 1) / BLK;
    k1_pre<<<gmain, BLK>>>();
    k2_zr<<<gmain, BLK>>>();
    k3_out<<<gmain, BLK>>>((float*)d_out);
}